// round 11
// baseline (speedup 1.0000x reference)
#include <cuda_runtime.h>
#include <cuda_fp16.h>
#include <cstdint>

#define EPS 1e-5f
#define B_  4
#define N_  512
#define M_  512
#define D_  128
#define H_  128
#define TN 8
#define TM 32
#define NTILES 4096          // 4 * 64 * 16
#define GRID 148
#define THREADS 512

// SMEM byte offsets
#define SM_W    0                      // fp16 W1d^T [h][k], swizzled, 32768 B
#define SM_XS   32768                  // fp16 x: 2 x 8*128*2   = 2 x 2048
#define SM_YS   (SM_XS + 4096)         // fp16 y: 2 x 32*136*2  = 2 x 8704
#define SM_XWS  (SM_YS + 17408)        // fp32:   2 x 4096
#define SM_YWS  (SM_XWS + 8192)        // fp32:   2 x 17408
#define SM_GAM  (SM_YWS + 34816)
#define SM_BET  (SM_GAM + 512)
#define SM_W2   (SM_BET + 512)
#define SMEM_BYTES (SM_W2 + 512)

#define YSTRIDE   136  // fp32 yw rows: floats per row
#define YSTRIDE_H 136  // fp16 y rows: halves per row

__device__ __forceinline__ uint32_t smem_u32(const void* p) {
    uint32_t a;
    asm("{ .reg .u64 t; cvta.to.shared.u64 t, %1; cvt.u32.u64 %0, t; }" : "=r"(a) : "l"(p));
    return a;
}
__device__ __forceinline__ void ldsm4(uint32_t* r, uint32_t addr) {
    asm volatile("ldmatrix.sync.aligned.m8n8.x4.shared.b16 {%0,%1,%2,%3}, [%4];"
        : "=r"(r[0]), "=r"(r[1]), "=r"(r[2]), "=r"(r[3]) : "r"(addr));
}
__device__ __forceinline__ void mma16816(float* c, const uint32_t* a,
                                         uint32_t b0, uint32_t b1) {
    asm volatile("mma.sync.aligned.m16n8k16.row.col.f32.f16.f16.f32 "
        "{%0,%1,%2,%3}, {%4,%5,%6,%7}, {%8,%9}, {%0,%1,%2,%3};"
        : "+f"(c[0]), "+f"(c[1]), "+f"(c[2]), "+f"(c[3])
        : "r"(a[0]), "r"(a[1]), "r"(a[2]), "r"(a[3]), "r"(b0), "r"(b1));
}
// swizzled offset into a [rows][128] fp16 tile (256 B/row, 16B-chunk XOR swizzle)
__device__ __forceinline__ uint32_t woff(int r, int k) {
    return (uint32_t)(r * 256 + ((((k >> 3) ^ (r & 7)) << 4)) + (k & 7) * 2);
}
__device__ __forceinline__ uint32_t h2u(__half2 h) {
    return *reinterpret_cast<uint32_t*>(&h);
}

// Scratch: xw = x@W1x + b1 (b1 ONLY here), yw = y@W1y
__device__ float g_xw[B_ * N_ * H_];
__device__ float g_yw[B_ * M_ * H_];

// ---------------------------------------------------------------------------
// Kernel 1: precompute xw/yw (fp32 exact)
// ---------------------------------------------------------------------------
__global__ __launch_bounds__(128) void precompute_kernel(
    const float* __restrict__ x, const float* __restrict__ y,
    const float* __restrict__ W1, const float* __restrict__ b1)
{
    const bool isY = blockIdx.x >= 256;
    const int r0 = (isY ? blockIdx.x - 256 : blockIdx.x) * 8;
    const float* __restrict__ src = isY ? y : x;
    const float* __restrict__ W = W1 + (isY ? D_ * H_ : 0);
    float* __restrict__ dst = isY ? g_yw : g_xw;

    __shared__ float v[8][D_];
    const int h = threadIdx.x;
    #pragma unroll
    for (int r = 0; r < 8; r++) v[r][h] = src[(r0 + r) * D_ + h];
    __syncthreads();

    float acc[8];
    const float bb = isY ? 0.f : b1[h];
    #pragma unroll
    for (int r = 0; r < 8; r++) acc[r] = bb;
    #pragma unroll 4
    for (int d = 0; d < D_; d++) {
        const float w = W[d * H_ + h];
        #pragma unroll
        for (int r = 0; r < 8; r++) acc[r] = fmaf(v[r][d], w, acc[r]);
    }
    #pragma unroll
    for (int r = 0; r < 8; r++) dst[(r0 + r) * H_ + h] = acc[r];
}

// ---------------------------------------------------------------------------
// Kernel 2: persistent HMMA kernel, m-split across warp pairs.
// Tile = 256 pairs (8n x 32m) x 128 h, K = 128. 16 warps:
// warp w -> n-row (w&7), m-half (w>>3)*16. 16 pairs x 128 h per warp.
// acc = 64 regs/thread; LN stays warp-local; no A-gen duplication.
// ---------------------------------------------------------------------------
__global__ void __launch_bounds__(THREADS, 1) main_kernel(
    const float* __restrict__ x, const float* __restrict__ y,
    const float* __restrict__ W1,
    const float* __restrict__ gamma, const float* __restrict__ beta,
    const float* __restrict__ W2, const float* __restrict__ b2,
    float* __restrict__ out)
{
    extern __shared__ char sm[];
    const int tid = threadIdx.x;
    const int wid = tid >> 5, lane = tid & 31;
    const int nw = wid & 7;          // n-row within tile
    const int mh = wid >> 3;         // m-half (0 or 1) -> m in [mh*16, mh*16+16)
    const int q = lane >> 2, c = lane & 3;

    // ---- one-time: W1d -> fp16 Wsm[h][k] swizzled ----
    {
        __half* wp = (__half*)sm;
        #pragma unroll
        for (int i = 0; i < 32; i++) {
            int e = i * 512 + tid;           // 16384 elements
            int k = e >> 7, h = e & 127;
            float v = W1[(2 * D_ + k) * H_ + h];
            *reinterpret_cast<__half*>((char*)wp + woff(h, k)) = __float2half_rn(v);
        }
    }
    if (tid < 128) {
        ((float*)(sm + SM_GAM))[tid] = gamma[tid];
        ((float*)(sm + SM_BET))[tid] = beta[tid];
        ((float*)(sm + SM_W2))[tid]  = W2[tid];
    }
    const float bias2 = b2[0];

    // per-lane ldmatrix B addressing constants
    const uint32_t wbase = smem_u32(sm);
    const int rp  = (((lane >> 4) & 1) << 3) + (lane & 7);
    const int kb8 = (lane >> 3) & 1;
    const int l7  = lane & 7;

    // tile loader: LDG fp32, convert, STS fp16 (x/y) + fp32 (xw/yw)
    auto load_tile = [&](int t, int sb) {
        const int bt = t >> 10, rem = t & 1023;
        const int n0 = (rem >> 4) * TN, m0 = (rem & 15) * TM;
        if (tid < 256) {
            float4 v = ((const float4*)(x + (bt * N_ + n0) * D_))[tid];
            __half2 h0 = __floats2half2_rn(v.x, v.y);
            __half2 h1 = __floats2half2_rn(v.z, v.w);
            uint2 pk = make_uint2(h2u(h0), h2u(h1));
            *(uint2*)((char*)sm + SM_XS + sb * 2048 + tid * 8) = pk;
            ((float4*)(sm + SM_XWS + sb * 4096))[tid] =
                ((const float4*)(g_xw + (bt * N_ + n0) * H_))[tid];
        }
        {
            const float* yg = y + (bt * M_ + m0) * D_;
            __half* ysb = (__half*)(sm + SM_YS + sb * 8704);
            const float* ywg = g_yw + (bt * M_ + m0) * H_;
            float* ywsb = (float*)(sm + SM_YWS + sb * 17408);
            #pragma unroll
            for (int j = 0; j < 2; j++) {
                int e = j * 512 + tid;
                int r = e >> 5, c4 = (e & 31) * 4;
                float4 v = *(const float4*)(yg + r * 128 + c4);
                __half2 h0 = __floats2half2_rn(v.x, v.y);
                __half2 h1 = __floats2half2_rn(v.z, v.w);
                uint2 pk = make_uint2(h2u(h0), h2u(h1));
                *(uint2*)(ysb + r * YSTRIDE_H + c4) = pk;
                *(float4*)(ywsb + r * YSTRIDE + c4) = *(const float4*)(ywg + r * 128 + c4);
            }
        }
    };

    load_tile(blockIdx.x, 0);
    __syncthreads();

    int iter = 0;
    for (int t = blockIdx.x; t < NTILES; t += GRID, iter++) {
        const int sb = iter & 1;
        const int bt = t >> 10, rem = t & 1023;
        const int n0 = (rem >> 4) * TN, m0 = (rem & 15) * TM;

        float acc[16][4];
        #pragma unroll
        for (int i = 0; i < 16; i++)
            #pragma unroll
            for (int j = 0; j < 4; j++) acc[i][j] = 0.f;

        const __half* xr  = (const __half*)(sm + SM_XS + sb * 2048) + nw * 128;
        // this warp's 16 m-rows start at mh*16; thread rows: q, q+8
        const __half* yra = (const __half*)(sm + SM_YS + sb * 8704)
                          + (mh * 16 + q) * YSTRIDE_H;
        const __half* yrb = yra + 8 * YSTRIDE_H;

        #pragma unroll
        for (int kt = 0; kt < 8; kt++) {
            const int k0 = kt * 16 + 2 * c;
            // ---- B fragments: all 8 h-tile-pairs (full H per warp) ----
            uint32_t br[8][4];
            const uint32_t kcol = (uint32_t)((((2 * kt + kb8) ^ l7) << 4));
            #pragma unroll
            for (int j = 0; j < 8; j++) {
                uint32_t addr = wbase + (uint32_t)((j * 16 + rp) * 256) + kcol;
                ldsm4(br[j], addr);
            }
            // ---- A-gen: one m16 fragment set (this warp's 16 pairs) ----
            uint32_t af[4];
            {
                __half2 x0 = *(const __half2*)(xr + k0);
                __half2 x1 = *(const __half2*)(xr + k0 + 8);
                __half2 a0 = *(const __half2*)(yra + k0);
                __half2 a1 = *(const __half2*)(yra + k0 + 8);
                __half2 b0 = *(const __half2*)(yrb + k0);
                __half2 b1 = *(const __half2*)(yrb + k0 + 8);
                af[0] = h2u(__habs2(__hsub2(x0, a0)));
                af[1] = h2u(__habs2(__hsub2(x0, b0)));
                af[2] = h2u(__habs2(__hsub2(x1, a1)));
                af[3] = h2u(__habs2(__hsub2(x1, b1)));
            }
            #pragma unroll
            for (int j = 0; j < 8; j++) {
                mma16816(acc[2*j],   af, br[j][0], br[j][1]);
                mma16816(acc[2*j+1], af, br[j][2], br[j][3]);
            }
        }

        // ---- prefetch next tile (other buffer) ----
        if (t + GRID < NTILES) load_tile(t + GRID, sb ^ 1);

        // ---- epilogue: 2 m-groups (m = q, q+8), LN warp-local ----
        {
            const float* xwr = (const float*)(sm + SM_XWS + sb * 4096) + nw * 128;
            const float* ywa = (const float*)(sm + SM_YWS + sb * 17408)
                             + (mh * 16 + q) * YSTRIDE;
            const float* ywb = ywa + 8 * YSTRIDE;
            const float* gm  = (const float*)(sm + SM_GAM);
            const float* be  = (const float*)(sm + SM_BET);
            const float* w2s = (const float*)(sm + SM_W2);

            // pass 1: add xw+yw in place, LN sums per m-group
            float s1a = 0.f, s2a = 0.f, s1b = 0.f, s2b = 0.f;
            #pragma unroll
            for (int nt = 0; nt < 16; nt++) {
                const int h = nt * 8 + 2 * c;
                float2 xw2 = *(const float2*)(xwr + h);
                float2 ya2 = *(const float2*)(ywa + h);
                float2 yb2 = *(const float2*)(ywb + h);
                float va0 = acc[nt][0] + xw2.x + ya2.x;
                float va1 = acc[nt][1] + xw2.y + ya2.y;
                float vb0 = acc[nt][2] + xw2.x + yb2.x;
                float vb1 = acc[nt][3] + xw2.y + yb2.y;
                acc[nt][0] = va0; acc[nt][1] = va1;
                acc[nt][2] = vb0; acc[nt][3] = vb1;
                s1a += va0 + va1; s2a = fmaf(va0, va0, fmaf(va1, va1, s2a));
                s1b += vb0 + vb1; s2b = fmaf(vb0, vb0, fmaf(vb1, vb1, s2b));
            }
            #pragma unroll
            for (int o = 1; o <= 2; o <<= 1) {
                s1a += __shfl_xor_sync(0xffffffffu, s1a, o);
                s2a += __shfl_xor_sync(0xffffffffu, s2a, o);
                s1b += __shfl_xor_sync(0xffffffffu, s1b, o);
                s2b += __shfl_xor_sync(0xffffffffu, s2b, o);
            }
            const float mua = s1a * (1.f / 128.f);
            const float mub = s1b * (1.f / 128.f);
            const float rsa = rsqrtf(s2a * (1.f / 128.f) - mua * mua + EPS);
            const float rsb = rsqrtf(s2b * (1.f / 128.f) - mub * mub + EPS);

            // pass 2: LN + relu + dot W2
            float oa = 0.f, ob = 0.f;
            #pragma unroll
            for (int nt = 0; nt < 16; nt++) {
                const int h = nt * 8 + 2 * c;
                float2 g2  = *(const float2*)(gm + h);
                float2 be2 = *(const float2*)(be + h);
                float2 w22 = *(const float2*)(w2s + h);
                float tv;
                tv = fmaf((acc[nt][0] - mua) * rsa, g2.x, be2.x);
                oa = fmaf(fmaxf(tv, 0.f), w22.x, oa);
                tv = fmaf((acc[nt][1] - mua) * rsa, g2.y, be2.y);
                oa = fmaf(fmaxf(tv, 0.f), w22.y, oa);
                tv = fmaf((acc[nt][2] - mub) * rsb, g2.x, be2.x);
                ob = fmaf(fmaxf(tv, 0.f), w22.x, ob);
                tv = fmaf((acc[nt][3] - mub) * rsb, g2.y, be2.y);
                ob = fmaf(fmaxf(tv, 0.f), w22.y, ob);
            }
            #pragma unroll
            for (int o = 1; o <= 2; o <<= 1) {
                oa += __shfl_xor_sync(0xffffffffu, oa, o);
                ob += __shfl_xor_sync(0xffffffffu, ob, o);
            }
            if (c == 0) {
                const int row = (bt * N_ + n0 + nw) * M_ + m0 + mh * 16;
                out[row + q]     = fmaxf(oa + bias2, 0.f);
                out[row + q + 8] = fmaxf(ob + bias2, 0.f);
            }
        }

        __syncthreads();   // all reads of buf[sb] done; prefetch STS visible
    }
}

// ---------------------------------------------------------------------------
extern "C" void kernel_launch(void* const* d_in, const int* in_sizes, int n_in,
                              void* d_out, int out_size)
{
    const float* x     = (const float*)d_in[0];
    const float* y     = (const float*)d_in[1];
    const float* W1    = (const float*)d_in[2];
    const float* b1    = (const float*)d_in[3];
    const float* gamma = (const float*)d_in[4];
    const float* beta  = (const float*)d_in[5];
    const float* W2    = (const float*)d_in[6];
    const float* b2    = (const float*)d_in[7];
    float* out = (float*)d_out;

    cudaFuncSetAttribute(main_kernel,
                         cudaFuncAttributeMaxDynamicSharedMemorySize, SMEM_BYTES);

    precompute_kernel<<<512, 128>>>(x, y, W1, b1);
    main_kernel<<<GRID, THREADS, SMEM_BYTES>>>(x, y, W1, gamma, beta, W2, b2, out);
}